// round 14
// baseline (speedup 1.0000x reference)
#include <cuda_runtime.h>
#include <cuda_fp16.h>
#include <math.h>

// Problem constants
#define BB     64
#define TT     2048
#define DD     40
#define HH     164
#define HP     192            // padded hidden (6 CTAs x 32 j)
#define XP     48             // padded x dim (l0)
#define NOUT   7
#define NCOL   6              // CTAs per layer
#define NLAYER 3
#define NCTA   (NCOL * NLAYER) // 18
#define TB     256             // 8 warps
#define RS     4               // h ring depth
#define NSLOT  8
#define AS     392             // A row stride (halves): 384 + 8 pad -> conflict-free ldsm
#define BS     72              // B row stride (halves): 64 + 8 pad

// ---- smem layout (bytes) ----
#define OFF_A   0              // A weights fp16 [128][AS]: 100352
#define OFF_B   100352         // B input fp16 [384][BS]: 55296 -> 155648
#define OFF_G   155648         // gates fp32 [128][68]: 34816 -> 190464  (Phase-A scratch too)
#define OFF_C   190464         // cell fp32 [32][64]: 8192 -> 198656
#define OFF_BI  198656         // bias fp32 [128]: 512 -> 199168
#define OFF_LEN 199168         // lengths: 256 -> 199424
#define SMEM_BYTES 199424

// ---------------- device scratch ----------------
__device__ __align__(256) __half g_xTh[TT * XP * BB];          // x fp16: [t][d48][b]
__device__ __align__(256) __half g_h[NLAYER * RS * HP * BB];   // h ring fp16: [l][slot][j][b]
__device__ unsigned g_flag[NCTA * 32];
__device__ __align__(128) unsigned g_cnt[NLAYER * NSLOT * 32];

// ---------------- helpers ----------------
__device__ __forceinline__ unsigned smem_u32(const void* p) {
    return (unsigned)__cvta_generic_to_shared(p);
}
__device__ __forceinline__ void ldsm_x4(unsigned& r0, unsigned& r1, unsigned& r2, unsigned& r3,
                                        unsigned addr) {
    asm volatile("ldmatrix.sync.aligned.m8n8.x4.shared.b16 {%0,%1,%2,%3}, [%4];"
                 : "=r"(r0), "=r"(r1), "=r"(r2), "=r"(r3) : "r"(addr));
}
__device__ __forceinline__ void ldsm_x4t(unsigned& r0, unsigned& r1, unsigned& r2, unsigned& r3,
                                         unsigned addr) {
    asm volatile("ldmatrix.sync.aligned.m8n8.x4.trans.shared.b16 {%0,%1,%2,%3}, [%4];"
                 : "=r"(r0), "=r"(r1), "=r"(r2), "=r"(r3) : "r"(addr));
}
__device__ __forceinline__ void mma16816(float* d, unsigned a0, unsigned a1, unsigned a2,
                                         unsigned a3, unsigned b0, unsigned b1) {
    asm volatile("mma.sync.aligned.m16n8k16.row.col.f32.f16.f16.f32 "
                 "{%0,%1,%2,%3}, {%4,%5,%6,%7}, {%8,%9}, {%0,%1,%2,%3};"
                 : "+f"(d[0]), "+f"(d[1]), "+f"(d[2]), "+f"(d[3])
                 : "r"(a0), "r"(a1), "r"(a2), "r"(a3), "r"(b0), "r"(b1));
}
__device__ __forceinline__ unsigned flag_acq(const unsigned* p) {
    unsigned r;
    asm volatile("ld.global.acquire.gpu.u32 %0, [%1];" : "=r"(r) : "l"(p));
    return r;
}
__device__ __forceinline__ void flag_rel(unsigned* p, unsigned v) {
    asm volatile("st.global.release.gpu.u32 [%0], %1;" :: "l"(p), "r"(v) : "memory");
}
__device__ __forceinline__ void cnt_add(unsigned* p) {
    asm volatile("red.release.gpu.global.add.u32 [%0], 1;" :: "l"(p) : "memory");
}
__device__ __forceinline__ void cnt_poll(const unsigned* p, unsigned tgt) {
    while (flag_acq(p) < tgt) { }
}
__device__ __forceinline__ unsigned cnt_tgt(int v) {
    return (unsigned)NCOL * ((unsigned)(v >> 3) + 1u);
}
__device__ __forceinline__ float sigf(float x) {
    float e = __expf(-x);
    return __fdividef(1.f, 1.f + e);
}
__device__ __forceinline__ float tanhfast(float z) {
    float e = __expf(-2.f * z);
    return __fdividef(2.f, 1.f + e) - 1.f;
}

// ---------------- persistent HMMA LSTM ----------------
__global__ void __launch_bounds__(TB, 1) k_lstm(
    const float* __restrict__ x,
    const int*   __restrict__ lengths,
    const float* __restrict__ Wih0, const float* __restrict__ Whh0, const float* __restrict__ bb0,
    const float* __restrict__ Wih1, const float* __restrict__ Whh1, const float* __restrict__ bb1,
    const float* __restrict__ Wih2, const float* __restrict__ Whh2, const float* __restrict__ bb2,
    const float* __restrict__ fcw,  const float* __restrict__ fcb,
    float* __restrict__ out)
{
    extern __shared__ char smem[];
    const unsigned smb = smem_u32(smem);
    __half* sA  = (__half*)(smem + OFF_A);
    __half* sB  = (__half*)(smem + OFF_B);
    float*  sG  = (float*)(smem + OFF_G);
    float*  sC  = (float*)(smem + OFF_C);
    float*  sBi = (float*)(smem + OFF_BI);
    int*    sLen= (int*)  (smem + OFF_LEN);

    const int tid  = threadIdx.x;
    const int cta  = blockIdx.x;
    const int l    = cta / NCOL;
    const int cb   = cta - l * NCOL;
    const int j0   = cb * 32;
    const int wid  = tid >> 5;
    const int lane = tid & 31;

    const unsigned base = g_flag[cta * 32];

    const float *Wih, *Whh, *bias;
    int KX;
    if (l == 0)      { Wih = Wih0; Whh = Whh0; bias = bb0; KX = XP; }
    else if (l == 1) { Wih = Wih1; Whh = Whh1; bias = bb1; KX = HP; }
    else             { Wih = Wih2; Whh = Whh2; bias = bb2; KX = HP; }
    const int K  = KX + HP;        // 240 or 384
    const int KC = K >> 4;         // 15 or 24 mma k-chunks

    // ---------- Phase A ----------
    // weights -> sA fp16 row-major [m][k], m = gate*32 + jj
    for (int m = 0; m < 128; ++m) {
        int g = m >> 5, jj = m & 31, j = j0 + jj;
        for (int k = tid; k < K; k += TB) {
            float w = 0.f;
            if (j < HH) {
                if (k < KX) {
                    if (l == 0) { if (k < DD) w = Wih[(g * HH + j) * DD + k]; }
                    else        { if (k < HH) w = Wih[(g * HH + j) * HH + k]; }
                } else {
                    int kk = k - KX;
                    if (kk < HH) w = Whh[(g * HH + j) * HH + kk];
                }
            }
            sA[m * AS + k] = __float2half_rn(w);
        }
    }
    if (tid < 128) {
        int g = tid >> 5, jj = tid & 31, j = j0 + jj;
        sBi[tid] = (j < HH) ? bias[g * HH + j] : 0.f;
    }
    if (tid < BB) sLen[tid] = lengths[tid];
    for (int i = tid; i < 32 * BB; i += TB) sC[i] = 0.f;
    if (cta == 0 && tid < NLAYER * NSLOT) g_cnt[tid * 32] = 0u;
    // zero h ring
    {
        unsigned* gh32 = (unsigned*)g_h;
        const int NH = (NLAYER * RS * HP * BB) / 2;
        for (int i = cta * TB + tid; i < NH; i += NCTA * TB) gh32[i] = 0u;
    }
    // x -> g_xTh [t][d48][b] fp16 via scratch transpose (reuse sG region)
    {
        float* scratch = sG;   // 64*48 floats = 12288 < 34816
        for (int t = cta; t < TT; t += NCTA) {
            __syncthreads();
            for (int i = tid; i < BB * DD; i += TB) {
                int b = i / DD, d = i - b * DD;
                scratch[b * XP + d] = x[(b * TT + t) * DD + d];
            }
            __syncthreads();
            for (int i = tid; i < XP * BB; i += TB) {
                int d = i >> 6, b = i & 63;
                g_xTh[(size_t)t * XP * BB + i] =
                    (d < DD) ? __float2half_rn(scratch[b * XP + d]) : __ushort_as_half(0);
            }
        }
    }
    __syncthreads();
    if (tid == 0) flag_rel(g_flag + cta * 32, base + 1);
    if (tid < NCTA) {
        while (flag_acq(g_flag + tid * 32) < base + 1) { }
    }
    __syncthreads();

    const int m0 = wid * 16;

    // ---------- main loop ----------
    for (int u = 0; u < TT; ++u) {
        // dependency polls (warp 0, parallel lanes) — proven R9 protocol
        if (wid == 0) {
            if (lane == 0 && l > 0)
                cnt_poll(g_cnt + ((l - 1) * NSLOT + (u & (NSLOT - 1))) * 32, cnt_tgt(u));
            if (lane == 1 && u >= 1)
                cnt_poll(g_cnt + (l * NSLOT + ((u - 1) & (NSLOT - 1))) * 32, cnt_tgt(u - 1));
            if (lane == 2 && l < NLAYER - 1 && u >= RS)
                cnt_poll(g_cnt + ((l + 1) * NSLOT + ((u - RS) & (NSLOT - 1))) * 32, cnt_tgt(u - RS));
        }
        __syncthreads();

        // ---- stage B [k][b] fp16: rows [0,KX) = x/producer-h, [KX,K) = own h(u-1) ----
        {
            const __half* xsrc = (l == 0)
                ? (g_xTh + (size_t)u * XP * BB)
                : (g_h + (size_t)((l - 1) * RS + (u & (RS - 1))) * HP * BB);
            const __half* hsrc = g_h + (size_t)(l * RS + ((u + RS - 1) & (RS - 1))) * HP * BB;
            const int sub = tid & 7;            // 8 threads per row, 16B each
            for (int row = tid >> 3; row < K; row += 32) {
                const __half* src = (row < KX) ? (xsrc + row * BB) : (hsrc + (row - KX) * BB);
                uint4 v = __ldcg((const uint4*)(src + sub * 8));
                *(uint4*)(sB + row * BS + sub * 8) = v;
            }
        }
        __syncthreads();

        // ---- GEMM: 8 warps, warp w -> gate rows m0..m0+15, all 64 batch ----
        {
            float acc[8][4];
            #pragma unroll
            for (int jt = 0; jt < 8; ++jt)
                #pragma unroll
                for (int q = 0; q < 4; ++q) acc[jt][q] = 0.f;

            for (int c = 0; c < KC; ++c) {
                unsigned a0, a1, a2, a3;
                unsigned aaddr = smb + OFF_A +
                    (unsigned)(((m0 + (lane & 15)) * AS + c * 16 + ((lane >> 4) << 3)) * 2);
                ldsm_x4(a0, a1, a2, a3, aaddr);
                const unsigned brow = (unsigned)(c * 16 + (lane & 15));
                const unsigned bcol = (unsigned)((lane >> 4) << 3);
                #pragma unroll
                for (int jt = 0; jt < 8; jt += 2) {
                    unsigned b0, b1, b2, b3;
                    unsigned baddr = smb + OFF_B +
                        (unsigned)((brow * BS + jt * 8 + bcol) * 2);
                    ldsm_x4t(b0, b1, b2, b3, baddr);
                    mma16816(acc[jt],     a0, a1, a2, a3, b0, b1);
                    mma16816(acc[jt + 1], a0, a1, a2, a3, b2, b3);
                }
            }

            // accumulators -> sG [m][68]
            const int r = lane >> 2;
            const int q = (lane & 3) * 2;
            #pragma unroll
            for (int jt = 0; jt < 8; ++jt) {
                *(float2*)&sG[(m0 + r)     * 68 + jt * 8 + q] = make_float2(acc[jt][0], acc[jt][1]);
                *(float2*)&sG[(m0 + r + 8) * 68 + jt * 8 + q] = make_float2(acc[jt][2], acc[jt][3]);
            }
        }
        __syncthreads();

        // ---- epilogue: 256 threads, thread -> (b, 8 j's) ----
        {
            const int b  = tid & 63;
            const int jg = tid >> 6;           // 0..3
            const bool mm = (u < sLen[b]);
            __half* hout = g_h + (size_t)(l * RS + (u & (RS - 1))) * HP * BB;
            #pragma unroll
            for (int qq = 0; qq < 8; ++qq) {
                int jj = jg * 8 + qq;
                float iv = sG[(0  + jj) * 68 + b] + sBi[jj];
                float fv = sG[(32 + jj) * 68 + b] + sBi[32 + jj];
                float gv = sG[(64 + jj) * 68 + b] + sBi[64 + jj];
                float ov = sG[(96 + jj) * 68 + b] + sBi[96 + jj];
                float co = sC[jj * BB + b];
                float cn = sigf(fv) * co + sigf(iv) * tanhfast(gv);
                float hn = sigf(ov) * tanhfast(cn);
                __half hpv = sB[(KX + j0 + jj) * BS + b];   // frozen bits (staged own h(u-1))
                sC[jj * BB + b] = mm ? cn : co;
                hout[(j0 + jj) * BB + b] = mm ? __float2half_rn(hn) : hpv;
            }
        }
        __syncthreads();

        if (tid == 0) cnt_add(g_cnt + (l * NSLOT + (u & (NSLOT - 1))) * 32);
    }

    // ---------- final FC on CTA 0 ----------
    if (cta == 0) {
        if (tid == 0) {
            const int v = TT - 1;
            cnt_poll(g_cnt + (2 * NSLOT + (v & (NSLOT - 1))) * 32, cnt_tgt(v));
        }
        __syncthreads();
        const __half* h2 = g_h + (size_t)(2 * RS + ((TT - 1) & (RS - 1))) * HP * BB;
        for (int it = tid; it < BB * NOUT; it += TB) {
            int b = it / NOUT, o = it - b * NOUT;
            float acc = fcb[o];
            for (int j = 0; j < HH; ++j) {
                unsigned short hv;
                asm volatile("ld.global.cg.u16 %0, [%1];" : "=h"(hv) : "l"(h2 + j * BB + b));
                acc += __half2float(__ushort_as_half(hv)) * fcw[o * HH + j];
            }
            out[b * NOUT + o] = acc;
        }
        __syncthreads();
    }

    if (tid == 0) flag_rel(g_flag + cta * 32, base + (unsigned)TT + 8);
}

// ---------------- launch ----------------
extern "C" void kernel_launch(void* const* d_in, const int* in_sizes, int n_in,
                              void* d_out, int out_size) {
    const float* x       = (const float*)d_in[0];
    const int*   lengths = (const int*)  d_in[1];
    const float* Wih0    = (const float*)d_in[2];
    const float* Whh0    = (const float*)d_in[3];
    const float* b0      = (const float*)d_in[4];
    const float* Wih1    = (const float*)d_in[5];
    const float* Whh1    = (const float*)d_in[6];
    const float* b1      = (const float*)d_in[7];
    const float* Wih2    = (const float*)d_in[8];
    const float* Whh2    = (const float*)d_in[9];
    const float* b2      = (const float*)d_in[10];
    const float* fcw     = (const float*)d_in[11];
    const float* fcb     = (const float*)d_in[12];
    float* out = (float*)d_out;

    static bool attr_set = false;
    if (!attr_set) {
        cudaFuncSetAttribute(k_lstm, cudaFuncAttributeMaxDynamicSharedMemorySize, SMEM_BYTES);
        attr_set = true;
    }

    k_lstm<<<NCTA, TB, SMEM_BYTES>>>(x, lengths,
                                     Wih0, Whh0, b0,
                                     Wih1, Whh1, b1,
                                     Wih2, Whh2, b2,
                                     fcw, fcb, out);
}